// round 9
// baseline (speedup 1.0000x reference)
#include <cuda_runtime.h>
#include <cuda_bf16.h>
#include <cstdint>

// ============================================================================
// GlobalAggregator — HMMA bf16 2-way split, drifting-warp weight pipeline
// R = B*N*K = 196608 rows (r = bn*12 + k)
// p1 : 384 thr/CTA, 96 rows = 8 bn per CTA, 2 CTA/SM.
//      Z = feat @ w1[0:256] (+wgt*w1[256]) -> lrelu -> ·w2 -> logits
//      -> in-CTA softmax over K=12 -> agg = Σ alpha·nbr -> g_agg
//      4-stage weight pipeline with consumed-mbarriers (no k-loop syncthreads)
// p2 : out = relu(concat(self, agg) @ w3)
// Weight smem: 32B rows (16 bf16), XOR swizzle -> conflict-free ldmatrix
// ============================================================================

#define KS1 16
#define KS2 32
#define CB  8192             // bytes per chunk half: 256 rows * 32B
#define NSTG1 4
#define NSTG2 3
#define NW1 12               // warps in p1 CTA

// ---- device scratch ----
__device__ __align__(128) unsigned short g_w1t_hi[KS1 * 4096];
__device__ __align__(128) unsigned short g_w1t_lo[KS1 * 4096];
__device__ __align__(128) unsigned short g_w3t_hi[KS2 * 4096];
__device__ __align__(128) unsigned short g_w3t_lo[KS2 * 4096];
__device__ __align__(16) float g_agg[16384 * 256];

// ---- smem offsets (bytes) ----
// mbarriers: full[s] @ sb+8s, empty[s] @ sb+64+8s
#define OFF_B(s)  (1024 + (s) * (2 * CB))
// p1 (NSTG1=4): B ends at 1024+65536=66560
#define OFF_W2    66560
#define OFF_W1L   67584
#define OFF_PART  68608      // 12 warps * 16 rows * 4B = 768
#define OFF_LOG   69376      // 96 floats
#define OFF_ALP   69760      // 96 floats
#define SMEM1     70144
// p2 (NSTG2=3): B ends at 1024+49152=50176
#define SMEM2     50176

// ============================================================================
// PTX helpers (baseline features only — nothing 'a'-gated)
// ============================================================================
__device__ __forceinline__ uint32_t smem_u32(const void* p) {
    uint32_t r;
    asm("{ .reg .u64 t; cvta.to.shared.u64 t, %1; cvt.u32.u64 %0, t; }"
        : "=r"(r) : "l"(p));
    return r;
}
__device__ __forceinline__ void mbar_init(uint32_t a, uint32_t cnt) {
    asm volatile("mbarrier.init.shared.b64 [%0], %1;" :: "r"(a), "r"(cnt) : "memory");
}
__device__ __forceinline__ void mbar_expect_tx(uint32_t a, uint32_t b) {
    asm volatile("mbarrier.arrive.expect_tx.shared.b64 _, [%0], %1;"
                 :: "r"(a), "r"(b) : "memory");
}
__device__ __forceinline__ void mbar_arrive(uint32_t a) {
    asm volatile("mbarrier.arrive.shared.b64 _, [%0];" :: "r"(a) : "memory");
}
__device__ __forceinline__ void mbar_wait(uint32_t a, uint32_t ph) {
    asm volatile(
        "{\n\t.reg .pred P;\n\t"
        "WL_%=:\n\t"
        "mbarrier.try_wait.parity.acquire.cta.shared::cta.b64 P, [%0], %1, 0x989680;\n\t"
        "@P bra.uni WD_%=;\n\t"
        "bra.uni WL_%=;\n\t"
        "WD_%=:\n\t}"
        :: "r"(a), "r"(ph) : "memory");
}
__device__ __forceinline__ void bulk_g2s(uint32_t dst, const void* src,
                                         uint32_t bytes, uint32_t mbar) {
    asm volatile(
        "cp.async.bulk.shared::cluster.global.mbarrier::complete_tx::bytes [%0], [%1], %2, [%3];"
        :: "r"(dst), "l"(src), "r"(bytes), "r"(mbar) : "memory");
}
__device__ __forceinline__ void ldsm4(uint32_t* r, uint32_t addr) {
    asm volatile("ldmatrix.sync.aligned.m8n8.x4.shared.b16 {%0,%1,%2,%3}, [%4];"
                 : "=r"(r[0]), "=r"(r[1]), "=r"(r[2]), "=r"(r[3]) : "r"(addr));
}
__device__ __forceinline__ void mma16816(float* c, const uint32_t* a,
                                         uint32_t b0, uint32_t b1) {
    asm volatile(
        "mma.sync.aligned.m16n8k16.row.col.f32.bf16.bf16.f32 "
        "{%0,%1,%2,%3}, {%4,%5,%6,%7}, {%8,%9}, {%0,%1,%2,%3};"
        : "+f"(c[0]), "+f"(c[1]), "+f"(c[2]), "+f"(c[3])
        : "r"(a[0]), "r"(a[1]), "r"(a[2]), "r"(a[3]), "r"(b0), "r"(b1));
}
__device__ __forceinline__ void split2(float v0, float v1, uint32_t& h, uint32_t& l) {
    __nv_bfloat162 hh = __floats2bfloat162_rn(v0, v1);
    float r0 = v0 - __bfloat162float(hh.x);
    float r1 = v1 - __bfloat162float(hh.y);
    __nv_bfloat162 ll = __floats2bfloat162_rn(r0, r1);
    h = *reinterpret_cast<uint32_t*>(&hh);
    l = *reinterpret_cast<uint32_t*>(&ll);
}

// ============================================================================
// prep: transpose + split weights into packed+swizzled [chunk][n][k16] rows
// ============================================================================
__global__ void prep_w1(const float* __restrict__ w1) {
    int i = blockIdx.x * blockDim.x + threadIdx.x;
    if (i >= KS1 * 256 * 16) return;
    int kk = i & 15, n = (i >> 4) & 255, c = i >> 12;
    float v = w1[(c * 16 + kk) * 256 + n];
    __nv_bfloat16 h = __float2bfloat16(v);
    __nv_bfloat16 l = __float2bfloat16(v - __bfloat162float(h));
    int dst = c * 4096 + n * 16 + (((kk >> 3) ^ ((n >> 2) & 1)) << 3) + (kk & 7);
    g_w1t_hi[dst] = __bfloat16_as_ushort(h);
    g_w1t_lo[dst] = __bfloat16_as_ushort(l);
}
__global__ void prep_w3(const float* __restrict__ w3) {
    int i = blockIdx.x * blockDim.x + threadIdx.x;
    if (i >= KS2 * 256 * 16) return;
    int kk = i & 15, n = (i >> 4) & 255, c = i >> 12;
    float v = w3[(c * 16 + kk) * 256 + n];
    __nv_bfloat16 h = __float2bfloat16(v);
    __nv_bfloat16 l = __float2bfloat16(v - __bfloat162float(h));
    int dst = c * 4096 + n * 16 + (((kk >> 3) ^ ((n >> 2) & 1)) << 3) + (kk & 7);
    g_w3t_hi[dst] = __bfloat16_as_ushort(h);
    g_w3t_lo[dst] = __bfloat16_as_ushort(l);
}

// ============================================================================
// Phase 1 — grid 2048, 384 thr (12 warps = 6 warp-pairs), 96 rows = 8 bn.
// ============================================================================
__global__ __launch_bounds__(384, 2)
void p1_kernel(const float* __restrict__ nbr, const float* __restrict__ wgt,
               const float* __restrict__ extra, const float* __restrict__ w1,
               const float* __restrict__ w2) {
    extern __shared__ char smem[];
    const uint32_t sb = smem_u32(smem);
    const int tid = threadIdx.x, wid = tid >> 5, lane = tid & 31;

    float* s_w2   = (float*)(smem + OFF_W2);
    float* s_w1l  = (float*)(smem + OFF_W1L);
    float* s_part = (float*)(smem + OFF_PART);
    float* s_log  = (float*)(smem + OFF_LOG);
    float* s_alp  = (float*)(smem + OFF_ALP);

    if (tid == 0) {
        for (int i = 0; i < NSTG1; i++) {
            mbar_init(sb + i * 8, 1);            // full[s]
            mbar_init(sb + 64 + i * 8, NW1);     // empty[s], one arrive per warp
        }
    }
    if (tid < 256) {
        s_w2[tid]  = w2[tid];
        s_w1l[tid] = w1[256 * 256 + tid];
    }
    __syncthreads();

    if (tid == 0) {
#pragma unroll
        for (int s = 0; s < NSTG1; s++) {
            mbar_expect_tx(sb + s * 8, 2 * CB);
            bulk_g2s(sb + OFF_B(s),      g_w1t_hi + s * 4096, CB, sb + s * 8);
            bulk_g2s(sb + OFF_B(s) + CB, g_w1t_lo + s * 4096, CB, sb + s * 8);
        }
    }

    const int  l4  = lane & 3, grp = lane >> 2;
    const long rt  = (long)blockIdx.x * 96 + (wid >> 1) * 16;  // tile base row
    const long r0  = rt + grp, r1 = rt + grp + 8;
    const long bnA = r0 / 12,  bnB = r1 / 12;
    const uint32_t nhoff = (wid & 1) * 4096;    // N-half: 128 rows * 32B
    const int ri = (((lane >> 3) & 2) << 2) + (lane & 7);
    const int kh = (lane >> 3) & 1;
    const uint32_t rowoff = ri * 32 + ((kh ^ ((ri >> 2) & 1)) << 4);

    float acc[64];
#pragma unroll
    for (int i = 0; i < 64; i++) acc[i] = 0.0f;

    float2 eA0, eA1, eB0, eB1, nA0, nA1, nB0, nB1;
    {
        const int k0 = l4 * 2;
        eA0 = *(const float2*)&extra[(bnA << 8) + k0];
        eA1 = *(const float2*)&extra[(bnA << 8) + k0 + 8];
        eB0 = *(const float2*)&extra[(bnB << 8) + k0];
        eB1 = *(const float2*)&extra[(bnB << 8) + k0 + 8];
        nA0 = *(const float2*)&nbr[(r0 << 8) + k0];
        nA1 = *(const float2*)&nbr[(r0 << 8) + k0 + 8];
        nB0 = *(const float2*)&nbr[(r1 << 8) + k0];
        nB1 = *(const float2*)&nbr[(r1 << 8) + k0 + 8];
    }

#pragma unroll 1
    for (int c = 0; c < KS1; c++) {
        const int s = c % NSTG1, ph = (c / NSTG1) & 1;

        uint32_t ah[4], al[4];
        split2(eA0.x * nA0.x, eA0.y * nA0.y, ah[0], al[0]);
        split2(eB0.x * nB0.x, eB0.y * nB0.y, ah[1], al[1]);
        split2(eA1.x * nA1.x, eA1.y * nA1.y, ah[2], al[2]);
        split2(eB1.x * nB1.x, eB1.y * nB1.y, ah[3], al[3]);

        if (c + 1 < KS1) {                       // prefetch next k-step
            const int k0 = (c + 1) * 16 + l4 * 2;
            eA0 = *(const float2*)&extra[(bnA << 8) + k0];
            eA1 = *(const float2*)&extra[(bnA << 8) + k0 + 8];
            eB0 = *(const float2*)&extra[(bnB << 8) + k0];
            eB1 = *(const float2*)&extra[(bnB << 8) + k0 + 8];
            nA0 = *(const float2*)&nbr[(r0 << 8) + k0];
            nA1 = *(const float2*)&nbr[(r0 << 8) + k0 + 8];
            nB0 = *(const float2*)&nbr[(r1 << 8) + k0];
            nB1 = *(const float2*)&nbr[(r1 << 8) + k0 + 8];
        }

        mbar_wait(sb + s * 8, ph);               // full[s]
        const uint32_t sBh = sb + OFF_B(s) + nhoff, sBl = sBh + CB;
#pragma unroll
        for (int np = 0; np < 8; np++) {
            uint32_t bh[4], bl[4];
            ldsm4(bh, sBh + np * 512 + rowoff);
            ldsm4(bl, sBl + np * 512 + rowoff);
            float* c0 = acc + np * 8;
            float* c1 = acc + np * 8 + 4;
            mma16816(c0, ah, bh[0], bh[1]);
            mma16816(c1, ah, bh[2], bh[3]);
            mma16816(c0, al, bh[0], bh[1]);
            mma16816(c1, al, bh[2], bh[3]);
            mma16816(c0, ah, bl[0], bl[1]);
            mma16816(c1, ah, bl[2], bl[3]);
        }
        if (lane == 0) mbar_arrive(sb + 64 + s * 8);   // consumed stage s
        if (tid == 0 && c + NSTG1 < KS1) {
            mbar_wait(sb + 64 + s * 8, ph);            // all warps consumed
            mbar_expect_tx(sb + s * 8, 2 * CB);
            bulk_g2s(sb + OFF_B(s),      g_w1t_hi + (c + NSTG1) * 4096, CB, sb + s * 8);
            bulk_g2s(sb + OFF_B(s) + CB, g_w1t_lo + (c + NSTG1) * 4096, CB, sb + s * 8);
        }
    }

    // ---- epilogue: + wgt[r]*w1[256], lrelu, ·w2, reduce over this N-half ----
    const int nh = (wid & 1) * 128;
    const float wr0 = wgt[r0];
    const float wr1 = wgt[r1];
    float p0 = 0.0f, p1 = 0.0f;
#pragma unroll
    for (int nt = 0; nt < 16; nt++) {
        const int col = nh + nt * 8 + l4 * 2;
        const float u0 = s_w1l[col], u1 = s_w1l[col + 1];
        const float v0 = s_w2[col],  v1 = s_w2[col + 1];
        float z;
        z = acc[nt * 4 + 0] + wr0 * u0; z = (z > 0.f) ? z : 0.2f * z; p0 = fmaf(z, v0, p0);
        z = acc[nt * 4 + 1] + wr0 * u1; z = (z > 0.f) ? z : 0.2f * z; p0 = fmaf(z, v1, p0);
        z = acc[nt * 4 + 2] + wr1 * u0; z = (z > 0.f) ? z : 0.2f * z; p1 = fmaf(z, v0, p1);
        z = acc[nt * 4 + 3] + wr1 * u1; z = (z > 0.f) ? z : 0.2f * z; p1 = fmaf(z, v1, p1);
    }
    p0 += __shfl_xor_sync(0xffffffffu, p0, 1);
    p0 += __shfl_xor_sync(0xffffffffu, p0, 2);
    p1 += __shfl_xor_sync(0xffffffffu, p1, 1);
    p1 += __shfl_xor_sync(0xffffffffu, p1, 2);
    if (l4 == 0) {
        s_part[wid * 16 + grp]     = p0;
        s_part[wid * 16 + 8 + grp] = p1;
    }
    __syncthreads();

    // combine warp-pair halves -> 96 logits
    if (tid < 96) {
        const int t = tid >> 4, i = tid & 15;
        s_log[t * 16 + i] = s_part[t * 32 + i] + s_part[t * 32 + 16 + i];
    }
    __syncthreads();

    // softmax over K=12 per bn (redundant per thread within bn group)
    if (tid < 96) {
        const int bn = tid / 12;
        const float* lg = &s_log[bn * 12];
        float m = lg[0];
#pragma unroll
        for (int i = 1; i < 12; i++) m = fmaxf(m, lg[i]);
        float se = 0.0f;
#pragma unroll
        for (int i = 0; i < 12; i++) se += expf(lg[i] - m);
        s_alp[tid] = expf(s_log[tid] - m) / se;
    }
    __syncthreads();

    // aggregation: 8 bn * 128 float2 columns = 1024 work items over 384 threads
    {
        const long bn0 = (long)blockIdx.x * 8;
#pragma unroll 1
        for (int i = tid; i < 1024; i += 384) {
            const int bn = i >> 7, dp = i & 127;
            const long rowbase = ((bn0 + bn) * 12) << 8;
            float ax = 0.0f, ay = 0.0f;
#pragma unroll
            for (int k = 0; k < 12; k++) {
                const float a = s_alp[bn * 12 + k];
                const float2 v = *(const float2*)&nbr[rowbase + (k << 8) + dp * 2];
                ax = fmaf(a, v.x, ax);
                ay = fmaf(a, v.y, ay);
            }
            float2 o; o.x = ax; o.y = ay;
            *(float2*)&g_agg[((bn0 + bn) << 8) + dp * 2] = o;
        }
    }
}

// ============================================================================
// Phase 2 — grid 256, 256 thr, 2 CTA/SM. Warp-pair per 16-row tile, N=128 half.
// ============================================================================
__global__ __launch_bounds__(256, 2)
void p2_kernel(const float* __restrict__ self_v, float* __restrict__ out) {
    extern __shared__ char smem[];
    const uint32_t sb = smem_u32(smem);
    const int tid = threadIdx.x, wid = tid >> 5, lane = tid & 31;

    if (tid == 0)
        for (int i = 0; i < NSTG2; i++) mbar_init(sb + i * 8, 1);
    __syncthreads();
    if (tid == 0) {
#pragma unroll
        for (int s = 0; s < NSTG2; s++) {
            mbar_expect_tx(sb + s * 8, 2 * CB);
            bulk_g2s(sb + OFF_B(s),      g_w3t_hi + s * 4096, CB, sb + s * 8);
            bulk_g2s(sb + OFF_B(s) + CB, g_w3t_lo + s * 4096, CB, sb + s * 8);
        }
    }

    const int l4 = lane & 3, grp = lane >> 2;
    const long m0 = (long)blockIdx.x * 64 + (wid >> 1) * 16 + grp, m1 = m0 + 8;
    const uint32_t nhoff = (wid & 1) * 4096;
    const int ri = (((lane >> 3) & 2) << 2) + (lane & 7);
    const int kh = (lane >> 3) & 1;
    const uint32_t rowoff = ri * 32 + ((kh ^ ((ri >> 2) & 1)) << 4);

    float acc[64];
#pragma unroll
    for (int i = 0; i < 64; i++) acc[i] = 0.0f;

    float2 nA0, nA1, nB0, nB1;
    {
        const int k0 = l4 * 2;
        nA0 = *(const float2*)&self_v[(m0 << 8) + k0];
        nA1 = *(const float2*)&self_v[(m0 << 8) + k0 + 8];
        nB0 = *(const float2*)&self_v[(m1 << 8) + k0];
        nB1 = *(const float2*)&self_v[(m1 << 8) + k0 + 8];
    }

#pragma unroll 1
    for (int c = 0; c < KS2; c++) {
        const int s = c % NSTG2, ph = (c / NSTG2) & 1;

        uint32_t ah[4], al[4];
        split2(nA0.x, nA0.y, ah[0], al[0]);
        split2(nB0.x, nB0.y, ah[1], al[1]);
        split2(nA1.x, nA1.y, ah[2], al[2]);
        split2(nB1.x, nB1.y, ah[3], al[3]);

        if (c + 1 < KS2) {
            const int cn = c + 1;
            const int k0 = (cn & 15) * 16 + l4 * 2;
            const float* base = (cn < 16) ? self_v : g_agg;
            nA0 = *(const float2*)&base[(m0 << 8) + k0];
            nA1 = *(const float2*)&base[(m0 << 8) + k0 + 8];
            nB0 = *(const float2*)&base[(m1 << 8) + k0];
            nB1 = *(const float2*)&base[(m1 << 8) + k0 + 8];
        }

        mbar_wait(sb + s * 8, ph);
        const uint32_t sBh = sb + OFF_B(s) + nhoff, sBl = sBh + CB;
#pragma unroll
        for (int np = 0; np < 8; np++) {
            uint32_t bh[4], bl[4];
            ldsm4(bh, sBh + np * 512 + rowoff);
            ldsm4(bl, sBl + np * 512 + rowoff);
            float* c0 = acc + np * 8;
            float* c1 = acc + np * 8 + 4;
            mma16816(c0, ah, bh[0], bh[1]);
            mma16816(c1, ah, bh[2], bh[3]);
            mma16816(c0, al, bh[0], bh[1]);
            mma16816(c1, al, bh[2], bh[3]);
            mma16816(c0, ah, bl[0], bl[1]);
            mma16816(c1, ah, bl[2], bl[3]);
        }
        __syncthreads();
        if (tid == 0 && c + NSTG2 < KS2) {
            mbar_expect_tx(sb + s * 8, 2 * CB);
            bulk_g2s(sb + OFF_B(s),      g_w3t_hi + (c + NSTG2) * 4096, CB, sb + s * 8);
            bulk_g2s(sb + OFF_B(s) + CB, g_w3t_lo + (c + NSTG2) * 4096, CB, sb + s * 8);
        }
    }

    const int nh = (wid & 1) * 128;
#pragma unroll
    for (int nt = 0; nt < 16; nt++) {
        const int col = nh + nt * 8 + l4 * 2;
        float2 o0 = make_float2(fmaxf(acc[nt * 4 + 0], 0.f), fmaxf(acc[nt * 4 + 1], 0.f));
        float2 o1 = make_float2(fmaxf(acc[nt * 4 + 2], 0.f), fmaxf(acc[nt * 4 + 3], 0.f));
        *(float2*)&out[(m0 << 8) + col] = o0;
        *(float2*)&out[(m1 << 8) + col] = o1;
    }
}

// ============================================================================
extern "C" void kernel_launch(void* const* d_in, const int* in_sizes, int n_in,
                              void* d_out, int out_size) {
    const float* self_v = (const float*)d_in[0];
    const float* nbr    = (const float*)d_in[1];
    // d_in[2] = masks (unused by reference)
    const float* wgt    = (const float*)d_in[3];
    const float* extra  = (const float*)d_in[4];
    const float* w1     = (const float*)d_in[5];
    const float* w2     = (const float*)d_in[6];
    const float* w3     = (const float*)d_in[7];
    float* out = (float*)d_out;

    cudaFuncSetAttribute(p1_kernel, cudaFuncAttributeMaxDynamicSharedMemorySize, SMEM1);
    cudaFuncSetAttribute(p2_kernel, cudaFuncAttributeMaxDynamicSharedMemorySize, SMEM2);

    prep_w1<<<256, 256>>>(w1);
    prep_w3<<<512, 256>>>(w3);
    p1_kernel<<<2048, 384, SMEM1>>>(nbr, wgt, extra, w1, w2);
    p2_kernel<<<256, 256, SMEM2>>>(self_v, out);
}

// round 13
// speedup vs baseline: 1.6143x; 1.6143x over previous
#include <cuda_runtime.h>
#include <cuda_bf16.h>
#include <cstdint>

// ============================================================================
// GlobalAggregator — HMMA bf16 2-way split, padding-free row tiling
// R = B*N*K = 196608 rows (r = bn*12 + k)
// p1 : Z = feat @ w1[0:256] (+wgt*w1[256] epi) -> lrelu -> ·w2 -> g_logit
//      256 thr/CTA, 64 rows/CTA, 2 CTA/SM, 4-stage DRIFTING weight pipeline
//      (consumed-mbarriers; no per-k-step __syncthreads)
// p1b: softmax over 12 + agg -> g_agg
// p2 : out = relu(concat(self, agg) @ w3)
// Weight smem: 32B rows (16 bf16), XOR swizzle -> conflict-free ldmatrix
// ============================================================================

#define KS1 16
#define KS2 32
#define CB  8192             // bytes per chunk half: 256 rows * 32B
#define NSTG1 4
#define NSTG2 3
#define NW1 8                // warps in p1 CTA

// ---- device scratch ----
__device__ __align__(128) unsigned short g_w1t_hi[KS1 * 4096];
__device__ __align__(128) unsigned short g_w1t_lo[KS1 * 4096];
__device__ __align__(128) unsigned short g_w3t_hi[KS2 * 4096];
__device__ __align__(128) unsigned short g_w3t_lo[KS2 * 4096];
__device__ __align__(16) float g_agg[16384 * 256];
__device__ __align__(16) float g_logit[196608];

// ---- smem offsets (bytes) ----
// p1: full[s] @ sb+8s, empty[s] @ sb+64+8s; B ends 1024+4*16384 = 66560
#define OFF_B(s)  (1024 + (s) * (2 * CB))
#define OFF_W2    66560
#define OFF_W1L   67584
#define OFF_PART  68608      // 8 warps * 16 rows * 4B = 512
#define SMEM1     69632
// p2 (NSTG2=3): B ends at 1024+49152=50176
#define SMEM2     50176

// ============================================================================
// PTX helpers (baseline features only — nothing 'a'-gated)
// ============================================================================
__device__ __forceinline__ uint32_t smem_u32(const void* p) {
    uint32_t r;
    asm("{ .reg .u64 t; cvta.to.shared.u64 t, %1; cvt.u32.u64 %0, t; }"
        : "=r"(r) : "l"(p));
    return r;
}
__device__ __forceinline__ void mbar_init(uint32_t a, uint32_t cnt) {
    asm volatile("mbarrier.init.shared.b64 [%0], %1;" :: "r"(a), "r"(cnt) : "memory");
}
__device__ __forceinline__ void mbar_expect_tx(uint32_t a, uint32_t b) {
    asm volatile("mbarrier.arrive.expect_tx.shared.b64 _, [%0], %1;"
                 :: "r"(a), "r"(b) : "memory");
}
__device__ __forceinline__ void mbar_arrive(uint32_t a) {
    asm volatile("mbarrier.arrive.shared.b64 _, [%0];" :: "r"(a) : "memory");
}
__device__ __forceinline__ void mbar_wait(uint32_t a, uint32_t ph) {
    asm volatile(
        "{\n\t.reg .pred P;\n\t"
        "WL_%=:\n\t"
        "mbarrier.try_wait.parity.acquire.cta.shared::cta.b64 P, [%0], %1, 0x989680;\n\t"
        "@P bra.uni WD_%=;\n\t"
        "bra.uni WL_%=;\n\t"
        "WD_%=:\n\t}"
        :: "r"(a), "r"(ph) : "memory");
}
__device__ __forceinline__ void bulk_g2s(uint32_t dst, const void* src,
                                         uint32_t bytes, uint32_t mbar) {
    asm volatile(
        "cp.async.bulk.shared::cluster.global.mbarrier::complete_tx::bytes [%0], [%1], %2, [%3];"
        :: "r"(dst), "l"(src), "r"(bytes), "r"(mbar) : "memory");
}
__device__ __forceinline__ void ldsm4(uint32_t* r, uint32_t addr) {
    asm volatile("ldmatrix.sync.aligned.m8n8.x4.shared.b16 {%0,%1,%2,%3}, [%4];"
                 : "=r"(r[0]), "=r"(r[1]), "=r"(r[2]), "=r"(r[3]) : "r"(addr));
}
__device__ __forceinline__ void mma16816(float* c, const uint32_t* a,
                                         uint32_t b0, uint32_t b1) {
    asm volatile(
        "mma.sync.aligned.m16n8k16.row.col.f32.bf16.bf16.f32 "
        "{%0,%1,%2,%3}, {%4,%5,%6,%7}, {%8,%9}, {%0,%1,%2,%3};"
        : "+f"(c[0]), "+f"(c[1]), "+f"(c[2]), "+f"(c[3])
        : "r"(a[0]), "r"(a[1]), "r"(a[2]), "r"(a[3]), "r"(b0), "r"(b1));
}
__device__ __forceinline__ void split2(float v0, float v1, uint32_t& h, uint32_t& l) {
    __nv_bfloat162 hh = __floats2bfloat162_rn(v0, v1);
    float r0 = v0 - __bfloat162float(hh.x);
    float r1 = v1 - __bfloat162float(hh.y);
    __nv_bfloat162 ll = __floats2bfloat162_rn(r0, r1);
    h = *reinterpret_cast<uint32_t*>(&hh);
    l = *reinterpret_cast<uint32_t*>(&ll);
}

// ============================================================================
// prep: transpose + split weights into packed+swizzled [chunk][n][k16] rows
// ushort index within chunk: n*16 + ((kh ^ ((n>>2)&1))<<3) + (kk&7)
// ============================================================================
__global__ void prep_w1(const float* __restrict__ w1) {
    int i = blockIdx.x * blockDim.x + threadIdx.x;
    if (i >= KS1 * 256 * 16) return;
    int kk = i & 15, n = (i >> 4) & 255, c = i >> 12;
    float v = w1[(c * 16 + kk) * 256 + n];
    __nv_bfloat16 h = __float2bfloat16(v);
    __nv_bfloat16 l = __float2bfloat16(v - __bfloat162float(h));
    int dst = c * 4096 + n * 16 + (((kk >> 3) ^ ((n >> 2) & 1)) << 3) + (kk & 7);
    g_w1t_hi[dst] = __bfloat16_as_ushort(h);
    g_w1t_lo[dst] = __bfloat16_as_ushort(l);
}
__global__ void prep_w3(const float* __restrict__ w3) {
    int i = blockIdx.x * blockDim.x + threadIdx.x;
    if (i >= KS2 * 256 * 16) return;
    int kk = i & 15, n = (i >> 4) & 255, c = i >> 12;
    float v = w3[(c * 16 + kk) * 256 + n];
    __nv_bfloat16 h = __float2bfloat16(v);
    __nv_bfloat16 l = __float2bfloat16(v - __bfloat162float(h));
    int dst = c * 4096 + n * 16 + (((kk >> 3) ^ ((n >> 2) & 1)) << 3) + (kk & 7);
    g_w3t_hi[dst] = __bfloat16_as_ushort(h);
    g_w3t_lo[dst] = __bfloat16_as_ushort(l);
}

// ============================================================================
// Phase 1 — grid 3072, 256 thr, 2 CTA/SM. Warp-pair per 16-row tile,
// each warp one N=128 half. Rows are global r (no padding).
// Drifting-warp pipeline: warps arrive on empty[s] after consuming; the
// producer (tid 0) waits all-consumed before refilling. No k-loop syncthreads.
// ============================================================================
__global__ __launch_bounds__(256, 2)
void p1_kernel(const float* __restrict__ nbr, const float* __restrict__ wgt,
               const float* __restrict__ extra, const float* __restrict__ w1,
               const float* __restrict__ w2) {
    extern __shared__ char smem[];
    const uint32_t sb = smem_u32(smem);
    const int tid = threadIdx.x, wid = tid >> 5, lane = tid & 31;

    float* s_w2   = (float*)(smem + OFF_W2);
    float* s_w1l  = (float*)(smem + OFF_W1L);
    float* s_part = (float*)(smem + OFF_PART);

    if (tid == 0) {
        for (int i = 0; i < NSTG1; i++) {
            mbar_init(sb + i * 8, 1);            // full[s]
            mbar_init(sb + 64 + i * 8, NW1);     // empty[s]
        }
    }
    s_w2[tid]  = w2[tid];
    s_w1l[tid] = w1[256 * 256 + tid];
    __syncthreads();

    if (tid == 0) {
#pragma unroll
        for (int s = 0; s < NSTG1; s++) {
            mbar_expect_tx(sb + s * 8, 2 * CB);
            bulk_g2s(sb + OFF_B(s),      g_w1t_hi + s * 4096, CB, sb + s * 8);
            bulk_g2s(sb + OFF_B(s) + CB, g_w1t_lo + s * 4096, CB, sb + s * 8);
        }
    }

    const int  l4  = lane & 3, grp = lane >> 2;
    const long rt  = (long)blockIdx.x * 64 + (wid >> 1) * 16;  // tile base row
    const long r0  = rt + grp, r1 = rt + grp + 8;
    const long bnA = r0 / 12,  bnB = r1 / 12;
    const uint32_t nhoff = (wid & 1) * 4096;    // N-half: 128 rows * 32B
    const int ri = (((lane >> 3) & 2) << 2) + (lane & 7);
    const int kh = (lane >> 3) & 1;
    const uint32_t rowoff = ri * 32 + ((kh ^ ((ri >> 2) & 1)) << 4);

    float acc[64];
#pragma unroll
    for (int i = 0; i < 64; i++) acc[i] = 0.0f;

    float2 eA0, eA1, eB0, eB1, nA0, nA1, nB0, nB1;
    {
        const int k0 = l4 * 2;
        eA0 = *(const float2*)&extra[(bnA << 8) + k0];
        eA1 = *(const float2*)&extra[(bnA << 8) + k0 + 8];
        eB0 = *(const float2*)&extra[(bnB << 8) + k0];
        eB1 = *(const float2*)&extra[(bnB << 8) + k0 + 8];
        nA0 = *(const float2*)&nbr[(r0 << 8) + k0];
        nA1 = *(const float2*)&nbr[(r0 << 8) + k0 + 8];
        nB0 = *(const float2*)&nbr[(r1 << 8) + k0];
        nB1 = *(const float2*)&nbr[(r1 << 8) + k0 + 8];
    }

#pragma unroll 1
    for (int c = 0; c < KS1; c++) {
        const int s = c % NSTG1, ph = (c / NSTG1) & 1;

        uint32_t ah[4], al[4];
        split2(eA0.x * nA0.x, eA0.y * nA0.y, ah[0], al[0]);
        split2(eB0.x * nB0.x, eB0.y * nB0.y, ah[1], al[1]);
        split2(eA1.x * nA1.x, eA1.y * nA1.y, ah[2], al[2]);
        split2(eB1.x * nB1.x, eB1.y * nB1.y, ah[3], al[3]);

        if (c + 1 < KS1) {                       // prefetch next k-step
            const int k0 = (c + 1) * 16 + l4 * 2;
            eA0 = *(const float2*)&extra[(bnA << 8) + k0];
            eA1 = *(const float2*)&extra[(bnA << 8) + k0 + 8];
            eB0 = *(const float2*)&extra[(bnB << 8) + k0];
            eB1 = *(const float2*)&extra[(bnB << 8) + k0 + 8];
            nA0 = *(const float2*)&nbr[(r0 << 8) + k0];
            nA1 = *(const float2*)&nbr[(r0 << 8) + k0 + 8];
            nB0 = *(const float2*)&nbr[(r1 << 8) + k0];
            nB1 = *(const float2*)&nbr[(r1 << 8) + k0 + 8];
        }

        mbar_wait(sb + s * 8, ph);               // full[s]
        const uint32_t sBh = sb + OFF_B(s) + nhoff, sBl = sBh + CB;
#pragma unroll
        for (int np = 0; np < 8; np++) {
            uint32_t bh[4], bl[4];
            ldsm4(bh, sBh + np * 512 + rowoff);
            ldsm4(bl, sBl + np * 512 + rowoff);
            float* c0 = acc + np * 8;
            float* c1 = acc + np * 8 + 4;
            mma16816(c0, ah, bh[0], bh[1]);
            mma16816(c1, ah, bh[2], bh[3]);
            mma16816(c0, al, bh[0], bh[1]);
            mma16816(c1, al, bh[2], bh[3]);
            mma16816(c0, ah, bl[0], bl[1]);
            mma16816(c1, ah, bl[2], bl[3]);
        }
        if (lane == 0) mbar_arrive(sb + 64 + s * 8);   // consumed stage s
        if (tid == 0 && c + NSTG1 < KS1) {
            mbar_wait(sb + 64 + s * 8, ph);            // all warps consumed
            mbar_expect_tx(sb + s * 8, 2 * CB);
            bulk_g2s(sb + OFF_B(s),      g_w1t_hi + (c + NSTG1) * 4096, CB, sb + s * 8);
            bulk_g2s(sb + OFF_B(s) + CB, g_w1t_lo + (c + NSTG1) * 4096, CB, sb + s * 8);
        }
    }

    // ---- epilogue: + wgt[r]*w1[256], lrelu, ·w2, reduce over this N-half ----
    const int nh = (wid & 1) * 128;
    const float wr0 = wgt[r0];
    const float wr1 = wgt[r1];
    float p0 = 0.0f, p1 = 0.0f;
#pragma unroll
    for (int nt = 0; nt < 16; nt++) {
        const int col = nh + nt * 8 + l4 * 2;
        const float u0 = s_w1l[col], u1 = s_w1l[col + 1];
        const float v0 = s_w2[col],  v1 = s_w2[col + 1];
        float z;
        z = acc[nt * 4 + 0] + wr0 * u0; z = (z > 0.f) ? z : 0.2f * z; p0 = fmaf(z, v0, p0);
        z = acc[nt * 4 + 1] + wr0 * u1; z = (z > 0.f) ? z : 0.2f * z; p0 = fmaf(z, v1, p0);
        z = acc[nt * 4 + 2] + wr1 * u0; z = (z > 0.f) ? z : 0.2f * z; p1 = fmaf(z, v0, p1);
        z = acc[nt * 4 + 3] + wr1 * u1; z = (z > 0.f) ? z : 0.2f * z; p1 = fmaf(z, v1, p1);
    }
    p0 += __shfl_xor_sync(0xffffffffu, p0, 1);
    p0 += __shfl_xor_sync(0xffffffffu, p0, 2);
    p1 += __shfl_xor_sync(0xffffffffu, p1, 1);
    p1 += __shfl_xor_sync(0xffffffffu, p1, 2);
    if (l4 == 0) {
        s_part[wid * 16 + grp]     = p0;
        s_part[wid * 16 + 8 + grp] = p1;
    }
    __syncthreads();
    if (tid < 64) {   // combine warp-pair halves: 4 tiles * 16 rows
        const int t = tid >> 4, i = tid & 15;
        g_logit[(long)blockIdx.x * 64 + t * 16 + i] =
            s_part[t * 32 + i] + s_part[t * 32 + 16 + i];
    }
}

// ============================================================================
// Phase 1b — softmax over K=12 + aggregation. grid 2048, warp per bn.
// ============================================================================
__global__ __launch_bounds__(256)
void p1b_kernel(const float* __restrict__ nbr) {
    const int tid = threadIdx.x, wid = tid >> 5, lane = tid & 31;
    const long bn = (long)blockIdx.x * 8 + wid;

    float lv = (lane < 12) ? g_logit[bn * 12 + lane] : -3.0e38f;
    float m = lv;
#pragma unroll
    for (int o = 16; o > 0; o >>= 1)
        m = fmaxf(m, __shfl_xor_sync(0xffffffffu, m, o));
    float e = (lane < 12) ? expf(lv - m) : 0.0f;
    float se = e;
#pragma unroll
    for (int o = 16; o > 0; o >>= 1)
        se += __shfl_xor_sync(0xffffffffu, se, o);
    const float a = e / se;

    const int d0 = lane * 8;
    float4 s0 = make_float4(0, 0, 0, 0), s1 = make_float4(0, 0, 0, 0);
#pragma unroll
    for (int k = 0; k < 12; k++) {
        const float ak = __shfl_sync(0xffffffffu, a, k);
        const float4* src = (const float4*)&nbr[((bn * 12 + k) << 8) + d0];
        float4 x = src[0], y = src[1];
        s0.x = fmaf(ak, x.x, s0.x); s0.y = fmaf(ak, x.y, s0.y);
        s0.z = fmaf(ak, x.z, s0.z); s0.w = fmaf(ak, x.w, s0.w);
        s1.x = fmaf(ak, y.x, s1.x); s1.y = fmaf(ak, y.y, s1.y);
        s1.z = fmaf(ak, y.z, s1.z); s1.w = fmaf(ak, y.w, s1.w);
    }
    float4* dst = (float4*)&g_agg[(bn << 8) + d0];
    dst[0] = s0; dst[1] = s1;
}

// ============================================================================
// Phase 2 — grid 256, 256 thr, 2 CTA/SM. Warp-pair per 16-row tile, N=128 half.
// ============================================================================
__global__ __launch_bounds__(256, 2)
void p2_kernel(const float* __restrict__ self_v, float* __restrict__ out) {
    extern __shared__ char smem[];
    const uint32_t sb = smem_u32(smem);
    const int tid = threadIdx.x, wid = tid >> 5, lane = tid & 31;

    if (tid == 0)
        for (int i = 0; i < NSTG2; i++) mbar_init(sb + i * 8, 1);
    __syncthreads();
    if (tid == 0) {
#pragma unroll
        for (int s = 0; s < NSTG2; s++) {
            mbar_expect_tx(sb + s * 8, 2 * CB);
            bulk_g2s(sb + OFF_B(s),      g_w3t_hi + s * 4096, CB, sb + s * 8);
            bulk_g2s(sb + OFF_B(s) + CB, g_w3t_lo + s * 4096, CB, sb + s * 8);
        }
    }

    const int l4 = lane & 3, grp = lane >> 2;
    const long m0 = (long)blockIdx.x * 64 + (wid >> 1) * 16 + grp, m1 = m0 + 8;
    const uint32_t nhoff = (wid & 1) * 4096;
    const int ri = (((lane >> 3) & 2) << 2) + (lane & 7);
    const int kh = (lane >> 3) & 1;
    const uint32_t rowoff = ri * 32 + ((kh ^ ((ri >> 2) & 1)) << 4);

    float acc[64];
#pragma unroll
    for (int i = 0; i < 64; i++) acc[i] = 0.0f;

    float2 nA0, nA1, nB0, nB1;
    {
        const int k0 = l4 * 2;
        nA0 = *(const float2*)&self_v[(m0 << 8) + k0];
        nA1 = *(const float2*)&self_v[(m0 << 8) + k0 + 8];
        nB0 = *(const float2*)&self_v[(m1 << 8) + k0];
        nB1 = *(const float2*)&self_v[(m1 << 8) + k0 + 8];
    }

#pragma unroll 1
    for (int c = 0; c < KS2; c++) {
        const int s = c % NSTG2, ph = (c / NSTG2) & 1;

        uint32_t ah[4], al[4];
        split2(nA0.x, nA0.y, ah[0], al[0]);
        split2(nB0.x, nB0.y, ah[1], al[1]);
        split2(nA1.x, nA1.y, ah[2], al[2]);
        split2(nB1.x, nB1.y, ah[3], al[3]);

        if (c + 1 < KS2) {
            const int cn = c + 1;
            const int k0 = (cn & 15) * 16 + l4 * 2;
            const float* base = (cn < 16) ? self_v : g_agg;
            nA0 = *(const float2*)&base[(m0 << 8) + k0];
            nA1 = *(const float2*)&base[(m0 << 8) + k0 + 8];
            nB0 = *(const float2*)&base[(m1 << 8) + k0];
            nB1 = *(const float2*)&base[(m1 << 8) + k0 + 8];
        }

        mbar_wait(sb + s * 8, ph);
        const uint32_t sBh = sb + OFF_B(s) + nhoff, sBl = sBh + CB;
#pragma unroll
        for (int np = 0; np < 8; np++) {
            uint32_t bh[4], bl[4];
            ldsm4(bh, sBh + np * 512 + rowoff);
            ldsm4(bl, sBl + np * 512 + rowoff);
            float* c0 = acc + np * 8;
            float* c1 = acc + np * 8 + 4;
            mma16816(c0, ah, bh[0], bh[1]);
            mma16816(c1, ah, bh[2], bh[3]);
            mma16816(c0, al, bh[0], bh[1]);
            mma16816(c1, al, bh[2], bh[3]);
            mma16816(c0, ah, bl[0], bl[1]);
            mma16816(c1, ah, bl[2], bl[3]);
        }
        __syncthreads();
        if (tid == 0 && c + NSTG2 < KS2) {
            mbar_expect_tx(sb + s * 8, 2 * CB);
            bulk_g2s(sb + OFF_B(s),      g_w3t_hi + (c + NSTG2) * 4096, CB, sb + s * 8);
            bulk_g2s(sb + OFF_B(s) + CB, g_w3t_lo + (c + NSTG2) * 4096, CB, sb + s * 8);
        }
    }

    const int nh = (wid & 1) * 128;
#pragma unroll
    for (int nt = 0; nt < 16; nt++) {
        const int col = nh + nt * 8 + l4 * 2;
        float2 o0 = make_float2(fmaxf(acc[nt * 4 + 0], 0.f), fmaxf(acc[nt * 4 + 1], 0.f));
        float2 o1 = make_float2(fmaxf(acc[nt * 4 + 2], 0.f), fmaxf(acc[nt * 4 + 3], 0.f));
        *(float2*)&out[(m0 << 8) + col] = o0;
        *(float2*)&out[(m1 << 8) + col] = o1;
    }
}

// ============================================================================
extern "C" void kernel_launch(void* const* d_in, const int* in_sizes, int n_in,
                              void* d_out, int out_size) {
    const float* self_v = (const float*)d_in[0];
    const float* nbr    = (const float*)d_in[1];
    // d_in[2] = masks (unused by reference)
    const float* wgt    = (const float*)d_in[3];
    const float* extra  = (const float*)d_in[4];
    const float* w1     = (const float*)d_in[5];
    const float* w2     = (const float*)d_in[6];
    const float* w3     = (const float*)d_in[7];
    float* out = (float*)d_out;

    cudaFuncSetAttribute(p1_kernel, cudaFuncAttributeMaxDynamicSharedMemorySize, SMEM1);
    cudaFuncSetAttribute(p2_kernel, cudaFuncAttributeMaxDynamicSharedMemorySize, SMEM2);

    prep_w1<<<256, 256>>>(w1);
    prep_w3<<<512, 256>>>(w3);
    p1_kernel<<<3072, 256, SMEM1>>>(nbr, wgt, extra, w1, w2);
    p1b_kernel<<<2048, 256>>>(nbr);
    p2_kernel<<<256, 256, SMEM2>>>(self_v, out);
}

// round 17
// speedup vs baseline: 1.6430x; 1.0177x over previous
#include <cuda_runtime.h>
#include <cuda_bf16.h>
#include <cstdint>

// ============================================================================
// GlobalAggregator — HMMA bf16 2-way split (3-pass), drift pipeline in p1,
// aggregation FUSED into p2 (overlaps 201MB nbr stream under p2 MMA).
// R = B*N*K = 196608 rows (r = bn*12 + k)
// p1 : Z = feat @ w1[0:256] (+wgt*w1[256] epi) -> lrelu -> ·w2 -> g_logit
// p2 : softmax(g_logit) -> agg (k-steps 0..15, interleaved) ;
//      out = relu(concat(self, agg) @ w3)
// ============================================================================

#define KS1 16
#define KS2 32
#define CB  8192             // bytes per chunk half: 256 rows * 32B
#define NSTG1 4
#define NSTG2 3
#define NW1 8                // warps in p1 CTA

// ---- device scratch ----
__device__ __align__(128) unsigned short g_w1t_hi[KS1 * 4096];
__device__ __align__(128) unsigned short g_w1t_lo[KS1 * 4096];
__device__ __align__(128) unsigned short g_w3t_hi[KS2 * 4096];
__device__ __align__(128) unsigned short g_w3t_lo[KS2 * 4096];
__device__ __align__(16) float g_agg[16384 * 256];
__device__ __align__(16) float g_logit[196608];

// ---- smem offsets (bytes) ----
// p1: full[s] @ sb+8s, empty[s] @ sb+64+8s; B ends 1024+4*16384 = 66560
#define OFF_B(s)  (1024 + (s) * (2 * CB))
#define OFF_W2    66560
#define OFF_W1L   67584
#define OFF_PART  68608      // 8 warps * 16 rows * 4B = 512
#define SMEM1     69632
// p2 (NSTG2=3): B ends at 1024+49152=50176 ; alphas after
#define OFF_ALP2  50176      // 64 bn * 12 floats = 3072 B
#define SMEM2     53248

// ============================================================================
// PTX helpers (baseline features only — nothing 'a'-gated)
// ============================================================================
__device__ __forceinline__ uint32_t smem_u32(const void* p) {
    uint32_t r;
    asm("{ .reg .u64 t; cvta.to.shared.u64 t, %1; cvt.u32.u64 %0, t; }"
        : "=r"(r) : "l"(p));
    return r;
}
__device__ __forceinline__ void mbar_init(uint32_t a, uint32_t cnt) {
    asm volatile("mbarrier.init.shared.b64 [%0], %1;" :: "r"(a), "r"(cnt) : "memory");
}
__device__ __forceinline__ void mbar_expect_tx(uint32_t a, uint32_t b) {
    asm volatile("mbarrier.arrive.expect_tx.shared.b64 _, [%0], %1;"
                 :: "r"(a), "r"(b) : "memory");
}
__device__ __forceinline__ void mbar_arrive(uint32_t a) {
    asm volatile("mbarrier.arrive.shared.b64 _, [%0];" :: "r"(a) : "memory");
}
__device__ __forceinline__ void mbar_wait(uint32_t a, uint32_t ph) {
    asm volatile(
        "{\n\t.reg .pred P;\n\t"
        "WL_%=:\n\t"
        "mbarrier.try_wait.parity.acquire.cta.shared::cta.b64 P, [%0], %1, 0x989680;\n\t"
        "@P bra.uni WD_%=;\n\t"
        "bra.uni WL_%=;\n\t"
        "WD_%=:\n\t}"
        :: "r"(a), "r"(ph) : "memory");
}
__device__ __forceinline__ void bulk_g2s(uint32_t dst, const void* src,
                                         uint32_t bytes, uint32_t mbar) {
    asm volatile(
        "cp.async.bulk.shared::cluster.global.mbarrier::complete_tx::bytes [%0], [%1], %2, [%3];"
        :: "r"(dst), "l"(src), "r"(bytes), "r"(mbar) : "memory");
}
__device__ __forceinline__ void ldsm4(uint32_t* r, uint32_t addr) {
    asm volatile("ldmatrix.sync.aligned.m8n8.x4.shared.b16 {%0,%1,%2,%3}, [%4];"
                 : "=r"(r[0]), "=r"(r[1]), "=r"(r[2]), "=r"(r[3]) : "r"(addr));
}
__device__ __forceinline__ void mma16816(float* c, const uint32_t* a,
                                         uint32_t b0, uint32_t b1) {
    asm volatile(
        "mma.sync.aligned.m16n8k16.row.col.f32.bf16.bf16.f32 "
        "{%0,%1,%2,%3}, {%4,%5,%6,%7}, {%8,%9}, {%0,%1,%2,%3};"
        : "+f"(c[0]), "+f"(c[1]), "+f"(c[2]), "+f"(c[3])
        : "r"(a[0]), "r"(a[1]), "r"(a[2]), "r"(a[3]), "r"(b0), "r"(b1));
}
__device__ __forceinline__ void split2(float v0, float v1, uint32_t& h, uint32_t& l) {
    __nv_bfloat162 hh = __floats2bfloat162_rn(v0, v1);
    float r0 = v0 - __bfloat162float(hh.x);
    float r1 = v1 - __bfloat162float(hh.y);
    __nv_bfloat162 ll = __floats2bfloat162_rn(r0, r1);
    h = *reinterpret_cast<uint32_t*>(&hh);
    l = *reinterpret_cast<uint32_t*>(&ll);
}

// ============================================================================
// prep: transpose + split weights into packed+swizzled [chunk][n][k16] rows
// ushort index within chunk: n*16 + ((kh ^ ((n>>2)&1))<<3) + (kk&7)
// ============================================================================
__global__ void prep_w1(const float* __restrict__ w1) {
    int i = blockIdx.x * blockDim.x + threadIdx.x;
    if (i >= KS1 * 256 * 16) return;
    int kk = i & 15, n = (i >> 4) & 255, c = i >> 12;
    float v = w1[(c * 16 + kk) * 256 + n];
    __nv_bfloat16 h = __float2bfloat16(v);
    __nv_bfloat16 l = __float2bfloat16(v - __bfloat162float(h));
    int dst = c * 4096 + n * 16 + (((kk >> 3) ^ ((n >> 2) & 1)) << 3) + (kk & 7);
    g_w1t_hi[dst] = __bfloat16_as_ushort(h);
    g_w1t_lo[dst] = __bfloat16_as_ushort(l);
}
__global__ void prep_w3(const float* __restrict__ w3) {
    int i = blockIdx.x * blockDim.x + threadIdx.x;
    if (i >= KS2 * 256 * 16) return;
    int kk = i & 15, n = (i >> 4) & 255, c = i >> 12;
    float v = w3[(c * 16 + kk) * 256 + n];
    __nv_bfloat16 h = __float2bfloat16(v);
    __nv_bfloat16 l = __float2bfloat16(v - __bfloat162float(h));
    int dst = c * 4096 + n * 16 + (((kk >> 3) ^ ((n >> 2) & 1)) << 3) + (kk & 7);
    g_w3t_hi[dst] = __bfloat16_as_ushort(h);
    g_w3t_lo[dst] = __bfloat16_as_ushort(l);
}

// ============================================================================
// Phase 1 — grid 3072, 256 thr, 2 CTA/SM. Warp-pair per 16-row tile,
// each warp one N=128 half. Drifting-warp pipeline (consumed-mbarriers).
// Byte-identical to the proven R13 kernel.
// ============================================================================
__global__ __launch_bounds__(256, 2)
void p1_kernel(const float* __restrict__ nbr, const float* __restrict__ wgt,
               const float* __restrict__ extra, const float* __restrict__ w1,
               const float* __restrict__ w2) {
    extern __shared__ char smem[];
    const uint32_t sb = smem_u32(smem);
    const int tid = threadIdx.x, wid = tid >> 5, lane = tid & 31;

    float* s_w2   = (float*)(smem + OFF_W2);
    float* s_w1l  = (float*)(smem + OFF_W1L);
    float* s_part = (float*)(smem + OFF_PART);

    if (tid == 0) {
        for (int i = 0; i < NSTG1; i++) {
            mbar_init(sb + i * 8, 1);            // full[s]
            mbar_init(sb + 64 + i * 8, NW1);     // empty[s]
        }
    }
    s_w2[tid]  = w2[tid];
    s_w1l[tid] = w1[256 * 256 + tid];
    __syncthreads();

    if (tid == 0) {
#pragma unroll
        for (int s = 0; s < NSTG1; s++) {
            mbar_expect_tx(sb + s * 8, 2 * CB);
            bulk_g2s(sb + OFF_B(s),      g_w1t_hi + s * 4096, CB, sb + s * 8);
            bulk_g2s(sb + OFF_B(s) + CB, g_w1t_lo + s * 4096, CB, sb + s * 8);
        }
    }

    const int  l4  = lane & 3, grp = lane >> 2;
    const long rt  = (long)blockIdx.x * 64 + (wid >> 1) * 16;  // tile base row
    const long r0  = rt + grp, r1 = rt + grp + 8;
    const long bnA = r0 / 12,  bnB = r1 / 12;
    const uint32_t nhoff = (wid & 1) * 4096;    // N-half: 128 rows * 32B
    const int ri = (((lane >> 3) & 2) << 2) + (lane & 7);
    const int kh = (lane >> 3) & 1;
    const uint32_t rowoff = ri * 32 + ((kh ^ ((ri >> 2) & 1)) << 4);

    float acc[64];
#pragma unroll
    for (int i = 0; i < 64; i++) acc[i] = 0.0f;

    float2 eA0, eA1, eB0, eB1, nA0, nA1, nB0, nB1;
    {
        const int k0 = l4 * 2;
        eA0 = *(const float2*)&extra[(bnA << 8) + k0];
        eA1 = *(const float2*)&extra[(bnA << 8) + k0 + 8];
        eB0 = *(const float2*)&extra[(bnB << 8) + k0];
        eB1 = *(const float2*)&extra[(bnB << 8) + k0 + 8];
        nA0 = *(const float2*)&nbr[(r0 << 8) + k0];
        nA1 = *(const float2*)&nbr[(r0 << 8) + k0 + 8];
        nB0 = *(const float2*)&nbr[(r1 << 8) + k0];
        nB1 = *(const float2*)&nbr[(r1 << 8) + k0 + 8];
    }

#pragma unroll 1
    for (int c = 0; c < KS1; c++) {
        const int s = c % NSTG1, ph = (c / NSTG1) & 1;

        uint32_t ah[4], al[4];
        split2(eA0.x * nA0.x, eA0.y * nA0.y, ah[0], al[0]);
        split2(eB0.x * nB0.x, eB0.y * nB0.y, ah[1], al[1]);
        split2(eA1.x * nA1.x, eA1.y * nA1.y, ah[2], al[2]);
        split2(eB1.x * nB1.x, eB1.y * nB1.y, ah[3], al[3]);

        if (c + 1 < KS1) {                       // prefetch next k-step
            const int k0 = (c + 1) * 16 + l4 * 2;
            eA0 = *(const float2*)&extra[(bnA << 8) + k0];
            eA1 = *(const float2*)&extra[(bnA << 8) + k0 + 8];
            eB0 = *(const float2*)&extra[(bnB << 8) + k0];
            eB1 = *(const float2*)&extra[(bnB << 8) + k0 + 8];
            nA0 = *(const float2*)&nbr[(r0 << 8) + k0];
            nA1 = *(const float2*)&nbr[(r0 << 8) + k0 + 8];
            nB0 = *(const float2*)&nbr[(r1 << 8) + k0];
            nB1 = *(const float2*)&nbr[(r1 << 8) + k0 + 8];
        }

        mbar_wait(sb + s * 8, ph);               // full[s]
        const uint32_t sBh = sb + OFF_B(s) + nhoff, sBl = sBh + CB;
#pragma unroll
        for (int np = 0; np < 8; np++) {
            uint32_t bh[4], bl[4];
            ldsm4(bh, sBh + np * 512 + rowoff);
            ldsm4(bl, sBl + np * 512 + rowoff);
            float* c0 = acc + np * 8;
            float* c1 = acc + np * 8 + 4;
            mma16816(c0, ah, bh[0], bh[1]);
            mma16816(c1, ah, bh[2], bh[3]);
            mma16816(c0, al, bh[0], bh[1]);
            mma16816(c1, al, bh[2], bh[3]);
            mma16816(c0, ah, bl[0], bl[1]);
            mma16816(c1, ah, bl[2], bl[3]);
        }
        if (lane == 0) mbar_arrive(sb + 64 + s * 8);   // consumed stage s
        if (tid == 0 && c + NSTG1 < KS1) {
            mbar_wait(sb + 64 + s * 8, ph);            // all warps consumed
            mbar_expect_tx(sb + s * 8, 2 * CB);
            bulk_g2s(sb + OFF_B(s),      g_w1t_hi + (c + NSTG1) * 4096, CB, sb + s * 8);
            bulk_g2s(sb + OFF_B(s) + CB, g_w1t_lo + (c + NSTG1) * 4096, CB, sb + s * 8);
        }
    }

    // ---- epilogue: + wgt[r]*w1[256], lrelu, ·w2, reduce over this N-half ----
    const int nh = (wid & 1) * 128;
    const float wr0 = wgt[r0];
    const float wr1 = wgt[r1];
    float p0 = 0.0f, p1 = 0.0f;
#pragma unroll
    for (int nt = 0; nt < 16; nt++) {
        const int col = nh + nt * 8 + l4 * 2;
        const float u0 = s_w1l[col], u1 = s_w1l[col + 1];
        const float v0 = s_w2[col],  v1 = s_w2[col + 1];
        float z;
        z = acc[nt * 4 + 0] + wr0 * u0; z = (z > 0.f) ? z : 0.2f * z; p0 = fmaf(z, v0, p0);
        z = acc[nt * 4 + 1] + wr0 * u1; z = (z > 0.f) ? z : 0.2f * z; p0 = fmaf(z, v1, p0);
        z = acc[nt * 4 + 2] + wr1 * u0; z = (z > 0.f) ? z : 0.2f * z; p1 = fmaf(z, v0, p1);
        z = acc[nt * 4 + 3] + wr1 * u1; z = (z > 0.f) ? z : 0.2f * z; p1 = fmaf(z, v1, p1);
    }
    p0 += __shfl_xor_sync(0xffffffffu, p0, 1);
    p0 += __shfl_xor_sync(0xffffffffu, p0, 2);
    p1 += __shfl_xor_sync(0xffffffffu, p1, 1);
    p1 += __shfl_xor_sync(0xffffffffu, p1, 2);
    if (l4 == 0) {
        s_part[wid * 16 + grp]     = p0;
        s_part[wid * 16 + 8 + grp] = p1;
    }
    __syncthreads();
    if (tid < 64) {   // combine warp-pair halves: 4 tiles * 16 rows
        const int t = tid >> 4, i = tid & 15;
        g_logit[(long)blockIdx.x * 64 + t * 16 + i] =
            s_part[t * 32 + i] + s_part[t * 32 + 16 + i];
    }
}

// ============================================================================
// Phase 2 — grid 256, 256 thr, 2 CTA/SM. Warp-pair per 16-row tile, N=128 half.
// FUSED aggregation: alphas from g_logit at start; agg for this CTA's 64 bns
// interleaved into k-steps 0..15 (1 float4 item per thread per step);
// per-k-step __syncthreads orders agg STGs before g_agg reads at c>=16.
// ============================================================================
__global__ __launch_bounds__(256, 2)
void p2_kernel(const float* __restrict__ self_v, const float* __restrict__ nbr,
               float* __restrict__ out) {
    extern __shared__ char smem[];
    const uint32_t sb = smem_u32(smem);
    const int tid = threadIdx.x, wid = tid >> 5, lane = tid & 31;
    float* s_alp = (float*)(smem + OFF_ALP2);

    if (tid == 0)
        for (int i = 0; i < NSTG2; i++) mbar_init(sb + i * 8, 1);
    __syncthreads();
    if (tid == 0) {
#pragma unroll
        for (int s = 0; s < NSTG2; s++) {
            mbar_expect_tx(sb + s * 8, 2 * CB);
            bulk_g2s(sb + OFF_B(s),      g_w3t_hi + s * 4096, CB, sb + s * 8);
            bulk_g2s(sb + OFF_B(s) + CB, g_w3t_lo + s * 4096, CB, sb + s * 8);
        }
    }

    // ---- softmax alphas for this CTA's 64 bns (768 values) ----
    {
        const float* lgbase = &g_logit[(long)blockIdx.x * 768];
#pragma unroll 1
        for (int i = tid; i < 768; i += 256) {
            const float* lg = lgbase + (i / 12) * 12;
            float m = lg[0];
#pragma unroll
            for (int j = 1; j < 12; j++) m = fmaxf(m, lg[j]);
            float se = 0.0f;
#pragma unroll
            for (int j = 0; j < 12; j++) se += expf(lg[j] - m);
            s_alp[i] = expf(lgbase[i] - m) / se;
        }
    }
    __syncthreads();

    const int l4 = lane & 3, grp = lane >> 2;
    const long m0 = (long)blockIdx.x * 64 + (wid >> 1) * 16 + grp, m1 = m0 + 8;
    const uint32_t nhoff = (wid & 1) * 4096;
    const int ri = (((lane >> 3) & 2) << 2) + (lane & 7);
    const int kh = (lane >> 3) & 1;
    const uint32_t rowoff = ri * 32 + ((kh ^ ((ri >> 2) & 1)) << 4);

    float acc[64];
#pragma unroll
    for (int i = 0; i < 64; i++) acc[i] = 0.0f;

    float2 nA0, nA1, nB0, nB1;
    {
        const int k0 = l4 * 2;
        nA0 = *(const float2*)&self_v[(m0 << 8) + k0];
        nA1 = *(const float2*)&self_v[(m0 << 8) + k0 + 8];
        nB0 = *(const float2*)&self_v[(m1 << 8) + k0];
        nB1 = *(const float2*)&self_v[(m1 << 8) + k0 + 8];
    }

#pragma unroll 1
    for (int c = 0; c < KS2; c++) {
        const int s = c % NSTG2, ph = (c / NSTG2) & 1;

        if (c == 16) {  // prefetch for c=16 was skipped (agg not ready then)
            const int k0 = l4 * 2;
            nA0 = *(const float2*)&g_agg[(m0 << 8) + k0];
            nA1 = *(const float2*)&g_agg[(m0 << 8) + k0 + 8];
            nB0 = *(const float2*)&g_agg[(m1 << 8) + k0];
            nB1 = *(const float2*)&g_agg[(m1 << 8) + k0 + 8];
        }

        uint32_t ah[4], al[4];
        split2(nA0.x, nA0.y, ah[0], al[0]);
        split2(nB0.x, nB0.y, ah[1], al[1]);
        split2(nA1.x, nA1.y, ah[2], al[2]);
        split2(nB1.x, nB1.y, ah[3], al[3]);

        if (c + 1 < KS2 && c + 1 != 16) {
            const int cn = c + 1;
            const int k0 = (cn & 15) * 16 + l4 * 2;
            const float* base = (cn < 16) ? self_v : g_agg;
            nA0 = *(const float2*)&base[(m0 << 8) + k0];
            nA1 = *(const float2*)&base[(m0 << 8) + k0 + 8];
            nB0 = *(const float2*)&base[(m1 << 8) + k0];
            nB1 = *(const float2*)&base[(m1 << 8) + k0 + 8];
        }

        mbar_wait(sb + s * 8, ph);
        const uint32_t sBh = sb + OFF_B(s) + nhoff, sBl = sBh + CB;
#pragma unroll
        for (int np = 0; np < 8; np++) {
            uint32_t bh[4], bl[4];
            ldsm4(bh, sBh + np * 512 + rowoff);
            ldsm4(bl, sBl + np * 512 + rowoff);
            float* c0 = acc + np * 8;
            float* c1 = acc + np * 8 + 4;
            mma16816(c0, ah, bh[0], bh[1]);
            mma16816(c1, ah, bh[2], bh[3]);
            mma16816(c0, al, bh[0], bh[1]);
            mma16816(c1, al, bh[2], bh[3]);
            mma16816(c0, ah, bl[0], bl[1]);
            mma16816(c1, ah, bl[2], bl[3]);
        }

        // ---- fused aggregation chunk (ksteps 0..15): 256 float4 items/step ----
        if (c < 16) {
            const int item = c * 256 + tid;       // 0..4095 = 64 bn * 64 col4
            const int bnl = item >> 6, c4 = (item & 63) << 2;
            const long bng = (long)blockIdx.x * 64 + bnl;
            float4 sA = make_float4(0, 0, 0, 0);
#pragma unroll
            for (int k = 0; k < 12; k++) {
                const float a = s_alp[bnl * 12 + k];
                const float4 v = *(const float4*)&nbr[((bng * 12 + k) << 8) + c4];
                sA.x = fmaf(a, v.x, sA.x);
                sA.y = fmaf(a, v.y, sA.y);
                sA.z = fmaf(a, v.z, sA.z);
                sA.w = fmaf(a, v.w, sA.w);
            }
            *(float4*)&g_agg[(bng << 8) + c4] = sA;
        }

        __syncthreads();
        if (tid == 0 && c + NSTG2 < KS2) {
            mbar_expect_tx(sb + s * 8, 2 * CB);
            bulk_g2s(sb + OFF_B(s),      g_w3t_hi + (c + NSTG2) * 4096, CB, sb + s * 8);
            bulk_g2s(sb + OFF_B(s) + CB, g_w3t_lo + (c + NSTG2) * 4096, CB, sb + s * 8);
        }
    }

    const int nh = (wid & 1) * 128;
#pragma unroll
    for (int nt = 0; nt < 16; nt++) {
        const int col = nh + nt * 8 + l4 * 2;
        float2 o0 = make_float2(fmaxf(acc[nt * 4 + 0], 0.f), fmaxf(acc[nt * 4 + 1], 0.f));
        float2 o1 = make_float2(fmaxf(acc[nt * 4 + 2], 0.f), fmaxf(acc[nt * 4 + 3], 0.f));
        *(float2*)&out[(m0 << 8) + col] = o0;
        *(float2*)&out[(m1 << 8) + col] = o1;
    }
}

// ============================================================================
extern "C" void kernel_launch(void* const* d_in, const int* in_sizes, int n_in,
                              void* d_out, int out_size) {
    const float* self_v = (const float*)d_in[0];
    const float* nbr    = (const float*)d_in[1];
    // d_in[2] = masks (unused by reference)
    const float* wgt    = (const float*)d_in[3];
    const float* extra  = (const float*)d_in[4];
    const float* w1     = (const float*)d_in[5];
    const float* w2     = (const float*)d_in[6];
    const float* w3     = (const float*)d_in[7];
    float* out = (float*)d_out;

    cudaFuncSetAttribute(p1_kernel, cudaFuncAttributeMaxDynamicSharedMemorySize, SMEM1);
    cudaFuncSetAttribute(p2_kernel, cudaFuncAttributeMaxDynamicSharedMemorySize, SMEM2);

    prep_w1<<<256, 256>>>(w1);
    prep_w3<<<512, 256>>>(w3);
    p1_kernel<<<3072, 256, SMEM1>>>(nbr, wgt, extra, w1, w2);
    p2_kernel<<<256, 256, SMEM2>>>(self_v, nbr, out);
}